// round 3
// baseline (speedup 1.0000x reference)
#include <cuda_runtime.h>

// Problem constants (fixed shapes per reference setup_inputs)
#define SS 512
#define DD 2640
#define MM 64
#define BB 8
// Only batch 7 contributes. Final scale = 1/(S*(S-1)) / M / (B*100)
// NOTE: mask_list is int32 on device (JAX x64 disabled downcasts jnp.int64).

// Kernel A tiling
#define ND     15      // d splits
#define DPC    176     // d per CTA (15*176 = 2640)
#define DCHUNK 88      // floats per staged chunk (2 chunks per CTA)
#define NPAIR  44      // float2 pairs per chunk
#define R2     130     // padded row length in float2 (128 rows + 2 pad)

__device__ float g_part[ND * MM * SS];   // 15*64*512 floats = 1.875 MB scratch
__device__ float g_mred[MM];

// ---------------------------------------------------------------------------
// Kernel A: partial sums of squared distances, f32x2-packed.
// Grid: (8 s-tiles, 15 d-splits). Block: 256 threads (tx = s-group, ty = m-group).
// Each thread owns a 4m x 4s register tile of packed accumulators.
// smem holds a transposed, d-pair-packed tile: trp[d2][row] with rows 0..63 = reh
// (target gathered rows), rows 64..127 = -inp (negated so diff = reh + (-inp)).
// ---------------------------------------------------------------------------
__global__ __launch_bounds__(256) void kA(const float* __restrict__ input,
                                          const int* __restrict__ mask,
                                          const float* __restrict__ target)
{
    __shared__ __align__(16) float2 trp[NPAIR * R2];   // 44*130*8 = 45760 B
    __shared__ const float* rowptr[128];

    const int tid = threadIdx.x;
    const int tx = tid & 15;          // s-group 0..15
    const int ty = tid >> 4;          // m-group 0..15
    const int sbase = blockIdx.x * 64;
    const int dbase = blockIdx.y * DPC;

    if (tid < 64) {
        int im = mask[7 * MM + tid];
        rowptr[tid] = target + ((size_t)7 * SS + (size_t)im) * DD + dbase;
    } else if (tid < 128) {
        int s = sbase + (tid - 64);
        rowptr[tid] = input + ((size_t)7 * SS + (size_t)s) * DD + dbase;
    }
    __syncthreads();

    unsigned long long acc[16];
    #pragma unroll
    for (int i = 0; i < 16; ++i) acc[i] = 0ull;   // float2(0,0) bit pattern

    for (int ch = 0; ch < 2; ++ch) {
        // ---- stage: 128 rows x 88 floats -> transposed packed smem ----
        // 128 rows * 22 float4 = 2816 float4 loads; exactly 11 per thread.
        #pragma unroll
        for (int k = 0; k < 11; ++k) {
            int i   = tid + k * 256;
            int row = i / 22;
            int c   = i - row * 22;
            const float4* src = reinterpret_cast<const float4*>(rowptr[row] + ch * DCHUNK) + c;
            float4 v = *src;
            if (row >= 64) { v.x = -v.x; v.y = -v.y; v.z = -v.z; v.w = -v.w; }
            trp[(2 * c    ) * R2 + row] = make_float2(v.x, v.y);
            trp[(2 * c + 1) * R2 + row] = make_float2(v.z, v.w);
        }
        __syncthreads();

        // ---- compute: 44 packed-d iterations ----
        #pragma unroll 2
        for (int d2 = 0; d2 < NPAIR; ++d2) {
            const float2* rb = trp + d2 * R2;
            ulonglong2 r01 = *reinterpret_cast<const ulonglong2*>(rb + 4 * ty);
            ulonglong2 r23 = *reinterpret_cast<const ulonglong2*>(rb + 4 * ty + 2);
            ulonglong2 i01 = *reinterpret_cast<const ulonglong2*>(rb + 64 + 4 * tx);
            ulonglong2 i23 = *reinterpret_cast<const ulonglong2*>(rb + 64 + 4 * tx + 2);
            unsigned long long rv[4] = { r01.x, r01.y, r23.x, r23.y };
            unsigned long long iv[4] = { i01.x, i01.y, i23.x, i23.y };
            #pragma unroll
            for (int a = 0; a < 4; ++a) {
                #pragma unroll
                for (int b = 0; b < 4; ++b) {
                    unsigned long long df;
                    asm("add.rn.f32x2 %0, %1, %2;" : "=l"(df) : "l"(rv[a]), "l"(iv[b]));
                    asm("fma.rn.f32x2 %0, %1, %1, %0;" : "+l"(acc[a * 4 + b]) : "l"(df));
                }
            }
        }
        __syncthreads();   // protect smem reuse by next chunk's staging
    }

    // ---- epilogue: fold packed halves, write partials (coalesced float4) ----
    float* outp = g_part + (size_t)blockIdx.y * (MM * SS);
    #pragma unroll
    for (int a = 0; a < 4; ++a) {
        int m = 4 * ty + a;
        float4 o;
        float* oc = &o.x;
        #pragma unroll
        for (int b = 0; b < 4; ++b) {
            unsigned long long v = acc[a * 4 + b];
            float lo = __uint_as_float((unsigned)(v & 0xffffffffu));
            float hi = __uint_as_float((unsigned)(v >> 32));
            oc[b] = lo + hi;
        }
        *reinterpret_cast<float4*>(outp + (size_t)m * SS + sbase + 4 * tx) = o;
    }
}

// ---------------------------------------------------------------------------
// Kernel B: per-m hinge + reduction over s. Grid: 64 CTAs (one per m).
// ---------------------------------------------------------------------------
__global__ __launch_bounds__(256) void kB(const int* __restrict__ mask)
{
    const int m   = blockIdx.x;
    const int tid = threadIdx.x;
    const int im  = mask[7 * MM + m];

    float lsum = 0.0f;
    for (int s = tid; s < SS; s += 256) {
        float sq = 0.0f;
        #pragma unroll
        for (int z = 0; z < ND; ++z)
            sq += g_part[(size_t)z * (MM * SS) + (size_t)m * SS + s];
        int d = im - s;
        if (d < 0) d = -d;
        float val = (d <= 1) ? sq : fmaxf(0.0f, 15000.0f - sq);
        lsum += val;
    }

    __shared__ float red[256];
    red[tid] = lsum;
    __syncthreads();
    for (int o = 128; o >= 1; o >>= 1) {
        if (tid < o) red[tid] += red[tid + o];
        __syncthreads();
    }
    if (tid == 0) g_mred[m] = red[0];
}

// ---------------------------------------------------------------------------
// Kernel C: final 64-way reduce + scaling. 1 block, 64 threads.
// ---------------------------------------------------------------------------
__global__ void kC(float* __restrict__ out)
{
    const int t = threadIdx.x;
    float v = g_mred[t];
    #pragma unroll
    for (int o = 16; o >= 1; o >>= 1)
        v += __shfl_down_sync(0xffffffffu, v, o);

    __shared__ float w[2];
    if ((t & 31) == 0) w[t >> 5] = v;
    __syncthreads();
    if (t == 0) {
        const float scale = (float)(1.0 / (261632.0 * 64.0 * 800.0)); // 1/(S(S-1)) /M /(B*100)
        out[0] = (w[0] + w[1]) * scale;
    }
}

// ---------------------------------------------------------------------------
extern "C" void kernel_launch(void* const* d_in, const int* in_sizes, int n_in,
                              void* d_out, int out_size)
{
    const float* input  = (const float*)d_in[0];
    const int*   mask   = (const int*)d_in[1];
    const float* target = (const float*)d_in[2];
    float*       out    = (float*)d_out;

    kA<<<dim3(8, ND), 256>>>(input, mask, target);
    kB<<<MM, 256>>>(mask);
    kC<<<1, 64>>>(out);
}

// round 5
// speedup vs baseline: 1.2145x; 1.2145x over previous
#include <cuda_runtime.h>

// Problem constants (fixed shapes per reference setup_inputs)
#define SS 512
#define DD 2640
#define MM 64
// Only batch 7 contributes. Final scale = 1/(S*(S-1)) / M / (B*100)
// mask_list is int32 on device (JAX x64 disabled downcasts jnp.int64).

// Kernel A tiling: grid (4 s-tiles, 30 d-splits) = 120 CTAs, 512 threads.
// Tile: 64 m x 128 s x 88 d per CTA, staged in 2 chunks of 44 d.
#define ND    30      // d splits
#define DPC   88      // d per CTA
#define NCH   2       // chunks per CTA
#define CHQ   11      // float4 (d-quads) per row per chunk
#define ROWS  192     // 64 target rows + 128 input rows
#define R4    193     // padded row stride in float4 units (odd -> conflict-free STS)
#define STILE 128     // s per CTA
#define NLD   5       // ceil(ROWS*CHQ / 512) staging loads per thread

__device__ float g_part[ND * MM * SS];   // 30*64*512 floats = 3.93 MB scratch
__device__ float g_mred[MM];

// ---------------------------------------------------------------------------
// Kernel A: partial sums of squared distances, f32x2-packed, register-buffered
// global->smem pipeline. smem layout: trp[q4][row], float4 = 4 consecutive d
// (2 packed f32x2). Rows 0..63 = gathered target rows, 64..191 = -input rows
// (negated so diff = reh + (-inp) is a single packed ADD).
// Thread (tx 0..31, ty 0..15) owns m = 4ty..4ty+3, s = tx+{0,32,64,96}.
// ---------------------------------------------------------------------------
__global__ __launch_bounds__(512) void kA(const float* __restrict__ input,
                                          const int* __restrict__ mask,
                                          const float* __restrict__ target)
{
    __shared__ __align__(16) float4 trp[CHQ * R4];   // 11*193*16 = 33968 B
    __shared__ const float* rowptr[ROWS];

    const int tid = threadIdx.x;
    const int tx = tid & 31;
    const int ty = tid >> 5;
    const int sbase = blockIdx.x * STILE;
    const int dbase = blockIdx.y * DPC;

    if (tid < MM) {
        int im = mask[7 * MM + tid];
        rowptr[tid] = target + ((size_t)7 * SS + (size_t)im) * DD + dbase;
    } else if (tid < ROWS) {
        rowptr[tid] = input + ((size_t)7 * SS + (size_t)(sbase + tid - MM)) * DD + dbase;
    }
    __syncthreads();

    unsigned long long acc[16];
    #pragma unroll
    for (int i = 0; i < 16; ++i) acc[i] = 0ull;   // float2(0,0)

    // prefetch chunk 0 into registers
    float4 buf[NLD];
    #pragma unroll
    for (int k = 0; k < NLD; ++k) {
        int i = tid + k * 512;
        if (i < ROWS * CHQ) {
            int row = i / CHQ, c = i - row * CHQ;
            float4 v = *(reinterpret_cast<const float4*>(rowptr[row]) + c);
            if (row >= MM) { v.x = -v.x; v.y = -v.y; v.z = -v.z; v.w = -v.w; }
            buf[k] = v;
        }
    }

    for (int ch = 0; ch < NCH; ++ch) {
        // ---- stage registers -> transposed smem (conflict-free: R4 odd) ----
        #pragma unroll
        for (int k = 0; k < NLD; ++k) {
            int i = tid + k * 512;
            if (i < ROWS * CHQ) {
                int row = i / CHQ, c = i - row * CHQ;
                trp[c * R4 + row] = buf[k];
            }
        }
        __syncthreads();

        // ---- prefetch next chunk (overlaps with compute below) ----
        if (ch + 1 < NCH) {
            #pragma unroll
            for (int k = 0; k < NLD; ++k) {
                int i = tid + k * 512;
                if (i < ROWS * CHQ) {
                    int row = i / CHQ, c = i - row * CHQ;
                    float4 v = *(reinterpret_cast<const float4*>(rowptr[row]) + (CHQ + c));
                    if (row >= MM) { v.x = -v.x; v.y = -v.y; v.z = -v.z; v.w = -v.w; }
                    buf[k] = v;
                }
            }
        }

        // ---- compute: 11 d-quad iterations, 64 packed fma-pipe ops each ----
        #pragma unroll 2
        for (int q = 0; q < CHQ; ++q) {
            const float4* base = trp + q * R4;
            ulonglong2 rv[4], iv[4];
            #pragma unroll
            for (int a = 0; a < 4; ++a)   // m rows: broadcast within warp
                rv[a] = *reinterpret_cast<const ulonglong2*>(base + 4 * ty + a);
            #pragma unroll
            for (int b = 0; b < 4; ++b)   // s rows: lane-contiguous
                iv[b] = *reinterpret_cast<const ulonglong2*>(base + MM + tx + 32 * b);
            #pragma unroll
            for (int a = 0; a < 4; ++a) {
                #pragma unroll
                for (int b = 0; b < 4; ++b) {
                    unsigned long long d0, d1;
                    asm("add.rn.f32x2 %0, %1, %2;" : "=l"(d0) : "l"(rv[a].x), "l"(iv[b].x));
                    asm("fma.rn.f32x2 %0, %1, %1, %0;" : "+l"(acc[a * 4 + b]) : "l"(d0));
                    asm("add.rn.f32x2 %0, %1, %2;" : "=l"(d1) : "l"(rv[a].y), "l"(iv[b].y));
                    asm("fma.rn.f32x2 %0, %1, %1, %0;" : "+l"(acc[a * 4 + b]) : "l"(d1));
                }
            }
        }
        __syncthreads();   // protect smem reuse by next chunk's staging
    }

    // ---- epilogue: fold packed halves, write partials (lane-coalesced) ----
    float* outp = g_part + (size_t)blockIdx.y * (MM * SS) + sbase;
    #pragma unroll
    for (int a = 0; a < 4; ++a) {
        int m = 4 * ty + a;
        #pragma unroll
        for (int b = 0; b < 4; ++b) {
            unsigned long long v = acc[a * 4 + b];
            float lo = __uint_as_float((unsigned)(v & 0xffffffffu));
            float hi = __uint_as_float((unsigned)(v >> 32));
            outp[(size_t)m * SS + tx + 32 * b] = lo + hi;
        }
    }
}

// ---------------------------------------------------------------------------
// Kernel B: per-m hinge + reduction over s. Grid: 64 CTAs (one per m).
// ---------------------------------------------------------------------------
__global__ __launch_bounds__(256) void kB(const int* __restrict__ mask)
{
    const int m   = blockIdx.x;
    const int tid = threadIdx.x;
    const int im  = mask[7 * MM + m];

    float lsum = 0.0f;
    for (int s = tid; s < SS; s += 256) {
        float sq = 0.0f;
        #pragma unroll
        for (int z = 0; z < ND; ++z)
            sq += g_part[(size_t)z * (MM * SS) + (size_t)m * SS + s];
        int d = im - s;
        if (d < 0) d = -d;
        float val = (d <= 1) ? sq : fmaxf(0.0f, 15000.0f - sq);
        lsum += val;
    }

    __shared__ float red[256];
    red[tid] = lsum;
    __syncthreads();
    for (int o = 128; o >= 1; o >>= 1) {
        if (tid < o) red[tid] += red[tid + o];
        __syncthreads();
    }
    if (tid == 0) g_mred[m] = red[0];
}

// ---------------------------------------------------------------------------
// Kernel C: final 64-way reduce + scaling. 1 block, 64 threads.
// ---------------------------------------------------------------------------
__global__ void kC(float* __restrict__ out)
{
    const int t = threadIdx.x;
    float v = g_mred[t];
    #pragma unroll
    for (int o = 16; o >= 1; o >>= 1)
        v += __shfl_down_sync(0xffffffffu, v, o);

    __shared__ float w[2];
    if ((t & 31) == 0) w[t >> 5] = v;
    __syncthreads();
    if (t == 0) {
        const float scale = (float)(1.0 / (261632.0 * 64.0 * 800.0)); // 1/(S(S-1)) /M /(B*100)
        out[0] = (w[0] + w[1]) * scale;
    }
}

// ---------------------------------------------------------------------------
extern "C" void kernel_launch(void* const* d_in, const int* in_sizes, int n_in,
                              void* d_out, int out_size)
{
    const float* input  = (const float*)d_in[0];
    const int*   mask   = (const int*)d_in[1];
    const float* target = (const float*)d_in[2];
    float*       out    = (float*)d_out;

    kA<<<dim3(4, ND), 512>>>(input, mask, target);
    kB<<<MM, 256>>>(mask);
    kC<<<1, 64>>>(out);
}